// round 13
// baseline (speedup 1.0000x reference)
#include <cuda_runtime.h>
#include <cuda_fp16.h>
#include <math.h>
#include <stdint.h>

#define EN 384
#define HIDN 128
#define NHEAD 8
#define DHEAD 16
#define NRBF 64

static constexpr int XROW = 272;  // fp16 tile row stride (bytes)
static constexpr int HROW = 320;  // fp16 HPRE row stride (bytes)

// ---- smem byte-offset map (dynamic smem, k_scores) ----
static constexpr int OFF_X1A  = 0;
static constexpr int OFF_X1B  = 34816;
static constexpr int OFF_W2H  = 69632;
static constexpr int OFF_HPREH= 104448;
static constexpr int OFF_SRED = 145408;
static constexpr int OFF_B2S  = 149504;
static constexpr int OFF_W3S  = 150016;
static constexpr int OFF_DISTS= 154112;
static constexpr int OFF_DOTS = 154624;
static constexpr int SMEM_BYTES = 155136;

// ---------------- device scratch ----------------
__device__ float g_v[EN * HIDN];
__device__ __half g_Aqh[NHEAD * EN * HIDN];
__device__ __half g_Akh[NHEAD * EN * HIDN];
__device__ __half g_W2h[HIDN * HIDN];
__device__ float g_gates[NHEAD * EN];
__device__ float g_scores[NHEAD * EN * EN];

__device__ __forceinline__ float siluf(float x) {
    return __fdividef(x, 1.0f + __expf(-x));
}
__device__ __forceinline__ uint32_t f16pair(float x0, float x1) {
    uint32_t u;
    asm("cvt.rn.f16x2.f32 %0, %1, %2;" : "=r"(u) : "f"(x1), "f"(x0));
    return u;
}
__device__ __forceinline__ uint32_t h2tanh(uint32_t y) {
    uint32_t r;
    asm("tanh.approx.f16x2 %0, %1;" : "=r"(r) : "r"(y));
    return r;
}
__device__ __forceinline__ uint32_t h2silu(uint32_t xb) {
    __half2 x = *(__half2*)&xb;
    __half2 y = __hmul2(x, __half2half2(__ushort_as_half(0x3800)));  // 0.5
    uint32_t yb = *(uint32_t*)&y;
    uint32_t tb = h2tanh(yb);
    __half2 t = *(__half2*)&tb;
    __half2 o = __hfma2(y, t, y);
    return *(uint32_t*)&o;
}
__device__ __forceinline__ uint32_t smem_u32(const void* p) {
    uint32_t a;
    asm("{ .reg .u64 t; cvta.to.shared.u64 t, %1; cvt.u32.u64 %0, t; }" : "=r"(a) : "l"(p));
    return a;
}

// ---- HMMA path ----
__device__ __forceinline__ void ldsm_x4(uint32_t* r, uint32_t addr) {
    asm volatile("ldmatrix.sync.aligned.m8n8.x4.shared.b16 {%0,%1,%2,%3}, [%4];"
                 : "=r"(r[0]), "=r"(r[1]), "=r"(r[2]), "=r"(r[3]) : "r"(addr));
}
__device__ __forceinline__ void ldsm_x4t(uint32_t* r, uint32_t addr) {
    asm volatile("ldmatrix.sync.aligned.m8n8.x4.trans.shared.b16 {%0,%1,%2,%3}, [%4];"
                 : "=r"(r[0]), "=r"(r[1]), "=r"(r[2]), "=r"(r[3]) : "r"(addr));
}
__device__ __forceinline__ void mma_f16(float* d, const uint32_t* a, uint32_t b0, uint32_t b1) {
    asm volatile(
        "mma.sync.aligned.m16n8k16.row.col.f32.f16.f16.f32 "
        "{%0,%1,%2,%3}, {%4,%5,%6,%7}, {%8,%9}, {%0,%1,%2,%3};"
        : "+f"(d[0]), "+f"(d[1]), "+f"(d[2]), "+f"(d[3])
        : "r"(a[0]), "r"(a[1]), "r"(a[2]), "r"(a[3]), "r"(b0), "r"(b1));
}

// ---------------- K_pre: 8 edges per block (1024 thr) + W2 convert block ----------------
__global__ void __launch_bounds__(1024, 1)
k_pre(const float* __restrict__ ef, const float* __restrict__ wq,
      const float* __restrict__ wk, const float* __restrict__ wv,
      const float* __restrict__ w1, const float* __restrict__ w2,
      const float* __restrict__ gw1, const float* __restrict__ gb1,
      const float* __restrict__ gw2, const float* __restrict__ gb2) {
    if (blockIdx.x == EN / 8) {   // W2 fp32 -> fp16 global, once
        for (int idx = threadIdx.x; idx < HIDN * HIDN; idx += blockDim.x)
            g_W2h[idx] = __float2half_rn(w2[idx]);
        return;
    }
    __shared__ float row[8][HIDN], qrow[8][HIDN], krow[8][HIDN], vrow[8][HIDN];
    __shared__ float wpart[8][4][NHEAD];
    int tid = threadIdx.x;
    int e = tid >> 7, n = tid & 127;
    int i = blockIdx.x * 8 + e;
    int lane = tid & 31;

    row[e][n] = ef[i * HIDN + n];
    __syncthreads();

    // q, k, v projections (weights shared across the 8 edge-groups via L1)
    {
        float qa = 0.f, ka = 0.f, va = 0.f;
#pragma unroll 4
        for (int c = 0; c < HIDN; c++) {
            float r = row[e][c];
            qa = fmaf(r, wq[c * HIDN + n], qa);
            ka = fmaf(r, wk[c * HIDN + n], ka);
            va = fmaf(r, wv[c * HIDN + n], va);
        }
        qrow[e][n] = qa; krow[e][n] = ka; vrow[e][n] = va;
        g_v[i * HIDN + n] = va;
    }
    __syncthreads();

    // Aq/Ak precompute (fp16 out)
#pragma unroll 1
    for (int h = 0; h < NHEAD; h++) {
        float aq = 0.f, ak = 0.f;
#pragma unroll
        for (int d = 0; d < DHEAD; d++) {
            aq = fmaf(qrow[e][h * DHEAD + d], w1[d * HIDN + n], aq);
            ak = fmaf(krow[e][h * DHEAD + d], w1[(DHEAD + d) * HIDN + n], ak);
        }
        g_Aqh[((long)h * EN + i) * HIDN + n] = __float2half_rn(aq);
        g_Akh[((long)h * EN + i) * HIDN + n] = __float2half_rn(ak);
    }
    // gates
#pragma unroll 1
    for (int h = 0; h < NHEAD; h++) {
        float acc = gb1[n];
#pragma unroll
        for (int d = 0; d < DHEAD; d++)
            acc = fmaf(vrow[e][h * DHEAD + d], gw1[d * HIDN + n], acc);
        float val = siluf(acc) * gw2[n];
#pragma unroll
        for (int off = 16; off > 0; off >>= 1)
            val += __shfl_xor_sync(0xffffffffu, val, off);
        if (lane == 0) wpart[e][(n >> 5)][h] = val;
    }
    __syncthreads();
    if (tid < 64) {
        int ee = tid >> 3, h = tid & 7;
        float s = wpart[ee][0][h] + wpart[ee][1][h] + wpart[ee][2][h] + wpart[ee][3][h];
        g_gates[h * EN + blockIdx.x * 8 + ee] = 1.0f / (1.0f + __expf(-(s + gb2[0])));
    }
}

// ---------------- K1: fused pair-MLP -> attention scores (unchanged) ----------------
__global__ void __launch_bounds__(1024, 1)
k_scores(const float* __restrict__ ec, const float* __restrict__ mask,
         const float* __restrict__ centers, const float* __restrict__ widths,
         const float* __restrict__ w1, const float* __restrict__ b1,
         const float* __restrict__ b2,
         const float* __restrict__ w3, const float* __restrict__ b3) {
    extern __shared__ float smem_f[];
    char* smem_c = (char*)smem_f;
    float* SRED  = (float*)(smem_c + OFF_SRED);
    float* B2S   = (float*)(smem_c + OFF_B2S);
    float* W3S   = (float*)(smem_c + OFF_W3S);
    float* dists = (float*)(smem_c + OFF_DISTS);
    float* dots  = (float*)(smem_c + OFF_DOTS);

    uint32_t sbase = smem_u32(smem_c);

    int tid = threadIdx.x;
    int w = tid >> 5, lane = tid & 31;
    int bi = blockIdx.x, bj = blockIdx.y;

    int p = tid >> 3;
    int lq = tid & 7;
    int ig_p = bi * 16 + (p >> 3);
    int jg_p = bj * 8 + (p & 7);

    if (tid < 128) {
        int pp = tid;
        int i = bi * 16 + (pp >> 3);
        int j = bj * 8 + (pp & 7);
        float ix = ec[i * 3], iy = ec[i * 3 + 1], iz = ec[i * 3 + 2];
        float jx = ec[j * 3], jy = ec[j * 3 + 1], jz = ec[j * 3 + 2];
        float dx = ix - jx, dy = iy - jy, dz = iz - jz;
        float d = sqrtf(dx * dx + dy * dy + dz * dz) + 1e-8f;
        d = fminf(fmaxf(d, 1e-8f), 1e8f);
        dists[pp] = d;
        float dt = ix * jx + iy * jy + iz * jz;
        dots[pp] = fminf(fmaxf(dt, -1e8f), 1e8f);
    }
    for (int idx = tid; idx < HIDN * HIDN / 8; idx += 1024) {
        int c = idx >> 4, col16 = idx & 15;
        *(uint4*)(smem_c + OFF_W2H + c * XROW + col16 * 16) =
            *(const uint4*)((const char*)g_W2h + idx * 16);
    }
    for (int idx = tid; idx < NRBF * HIDN; idx += 1024) {
        int r = idx >> 7, n = idx & 127;
        __half hv = __float2half_rn(w1[(2 * DHEAD + r) * HIDN + n]);
        *(unsigned short*)(smem_c + OFF_X1B + r * XROW + n * 2) = __half_as_ushort(hv);
    }
    if (tid < 128) B2S[tid] = b2[tid];
    for (int idx = tid; idx < HIDN * NHEAD; idx += 1024) W3S[idx] = w3[idx];
    __syncthreads();

    for (int idx = tid; idx < 128 * (NRBF / 2); idx += 1024) {
        int pp = idx >> 5, rp = idx & 31;
        int r = 2 * rp;
        float d = dists[pp];
        float t0 = d - centers[r], t1 = d - centers[r + 1];
        float e0 = 0.f, e1 = 0.f;
        if (d <= 10.0f) {
            e0 = __expf(-widths[r] * t0 * t0);
            e1 = __expf(-widths[r + 1] * t1 * t1);
        }
        *(uint32_t*)(smem_c + OFF_X1A + pp * XROW + r * 2) = f16pair(e0, e1);
    }
    __syncthreads();

    int mb = w & 7, nb = w >> 3;
    int r16 = lane & 15, rh = lane >> 4;
    uint32_t aTile = (uint32_t)(16 * mb + r16) * XROW + rh * 16;
    uint32_t bW1 = sbase + OFF_X1B + (uint32_t)r16 * XROW + 64 * nb + 16 * rh;
    uint32_t bHi = sbase + OFF_W2H + (uint32_t)r16 * XROW + 64 * nb + 16 * rh;

    // rbf -> hpre via HMMA (K = 64)
    {
        uint32_t aRbf = sbase + OFF_X1A + aTile;
        float acc[4][4];
#pragma unroll
        for (int ni = 0; ni < 4; ni++)
#pragma unroll
            for (int e = 0; e < 4; e++) acc[ni][e] = 0.f;
#pragma unroll
        for (int kk = 0; kk < 4; kk++) {
            uint32_t ah[4], bh[2][4];
            ldsm_x4(ah, aRbf + kk * 32);
            ldsm_x4t(bh[0], bW1 + kk * 16 * XROW);
            ldsm_x4t(bh[1], bW1 + kk * 16 * XROW + 32);
#pragma unroll
            for (int bx = 0; bx < 2; bx++)
#pragma unroll
                for (int hf = 0; hf < 2; hf++) {
                    int ni = 2 * bx + hf;
                    mma_f16(acc[ni], ah, bh[bx][2 * hf], bh[bx][2 * hf + 1]);
                }
        }
        int r0 = 16 * mb + (lane >> 2);
        float dp0 = dots[r0], dp1 = dots[r0 + 8];
#pragma unroll
        for (int ni = 0; ni < 4; ni++) {
            int c0 = 32 * nb + 8 * ni + 2 * (lane & 3);
            float wd0 = __ldg(w1 + 96 * HIDN + c0), wd1 = __ldg(w1 + 96 * HIDN + c0 + 1);
            float b10 = __ldg(b1 + c0), b11 = __ldg(b1 + c0 + 1);
            float v00 = acc[ni][0] + dp0 * wd0 + b10;
            float v01 = acc[ni][1] + dp0 * wd1 + b11;
            float v10 = acc[ni][2] + dp1 * wd0 + b10;
            float v11 = acc[ni][3] + dp1 * wd1 + b11;
            *(uint32_t*)(smem_c + OFF_HPREH + r0 * HROW + c0 * 2) = f16pair(v00, v01);
            *(uint32_t*)(smem_c + OFF_HPREH + (r0 + 8) * HROW + c0 * 2) = f16pair(v10, v11);
        }
    }
    __syncthreads();

    uint32_t aTileX = aTile;
    float mask_v = 0.f;
    int igw = 0, jgw = 0;
    if (tid < 128) {
        igw = bi * 16 + (tid >> 3);
        jgw = bj * 8 + (tid & 7);
        mask_v = __ldg(mask + (long)igw * EN + jgw);
    }

    const char* hpb = smem_c + OFF_HPREH + p * HROW;
    auto build_x1 = [&](int h, int sel) {
        char* dst = smem_c + (sel ? OFF_X1B : OFF_X1A) + p * XROW;
        const __half* aqp = g_Aqh + ((long)(h * EN + ig_p)) * HIDN;
        const __half* akp = g_Akh + ((long)(h * EN + jg_p)) * HIDN;
#pragma unroll
        for (int q = 0; q < 4; q++) {
            int c = lq * 4 + 32 * q;
            uint2 av = __ldg((const uint2*)(aqp + c));
            uint2 kv = __ldg((const uint2*)(akp + c));
            uint2 hv = *(const uint2*)(hpb + c * 2);
            __half2 x0 = __hadd2(__hadd2(*(__half2*)&hv.x, *(__half2*)&av.x),
                                 *(__half2*)&kv.x);
            __half2 x1 = __hadd2(__hadd2(*(__half2*)&hv.y, *(__half2*)&av.y),
                                 *(__half2*)&kv.y);
            uint32_t o0 = h2silu(*(uint32_t*)&x0);
            uint32_t o1 = h2silu(*(uint32_t*)&x1);
            *(uint2*)(dst + c * 2) = make_uint2(o0, o1);
        }
    };

    build_x1(0, 0);
    __syncthreads();

    for (int h = 0; h < NHEAD; h++) {
        int sel = h & 1;
        uint32_t aBuf = sbase + (sel ? OFF_X1B : OFF_X1A) + aTileX;
        float acc[4][4];
#pragma unroll
        for (int ni = 0; ni < 4; ni++)
#pragma unroll
            for (int e = 0; e < 4; e++) acc[ni][e] = 0.f;

#pragma unroll
        for (int kk = 0; kk < 8; kk++) {
            uint32_t kab = (uint32_t)kk * 32;
            uint32_t kbb = (uint32_t)kk * 16 * XROW;
            uint32_t ah[4], bh[2][4];
            ldsm_x4(ah, aBuf + kab);
            ldsm_x4t(bh[0], bHi + kbb);
            ldsm_x4t(bh[1], bHi + kbb + 32);
#pragma unroll
            for (int bx = 0; bx < 2; bx++)
#pragma unroll
                for (int hf = 0; hf < 2; hf++) {
                    int ni = 2 * bx + hf;
                    mma_f16(acc[ni], ah, bh[bx][2 * hf], bh[bx][2 * hf + 1]);
                }
        }

        {
            float* SR = SRED + sel * 512;
            int colq = 2 * (lane & 3);
            float s0 = 0.f, s1 = 0.f;
#pragma unroll
            for (int ni = 0; ni < 4; ni++) {
                int col = 32 * nb + 8 * ni + colq;
                float b2a = B2S[col], b2b = B2S[col + 1];
                float w3a = W3S[col * NHEAD + h], w3b = W3S[(col + 1) * NHEAD + h];
                uint32_t u0 = h2silu(f16pair(acc[ni][0] + b2a, acc[ni][1] + b2b));
                float2 f0 = __half22float2(*(__half2*)&u0);
                s0 += f0.x * w3a + f0.y * w3b;
                uint32_t u1 = h2silu(f16pair(acc[ni][2] + b2a, acc[ni][3] + b2b));
                float2 f1 = __half22float2(*(__half2*)&u1);
                s1 += f1.x * w3a + f1.y * w3b;
            }
#pragma unroll
            for (int off = 1; off < 4; off <<= 1) {
                s0 += __shfl_xor_sync(0xffffffffu, s0, off);
                s1 += __shfl_xor_sync(0xffffffffu, s1, off);
            }
            if ((lane & 3) == 0) {
                int r0 = 16 * mb + (lane >> 2);
                SR[nb * 128 + r0] = s0;
                SR[nb * 128 + r0 + 8] = s1;
            }
        }

        if (h < NHEAD - 1) build_x1(h + 1, sel ^ 1);

        __syncthreads();

        if (tid < 128) {
            float* SR = SRED + sel * 512;
            float tot = SR[tid] + SR[128 + tid] + SR[256 + tid] + SR[384 + tid];
            float sc = tot + b3[h] + mask_v;
            sc = fminf(fmaxf(sc, -1e9f), 1e9f);
            g_scores[((long)h * EN + igw) * EN + jgw] = sc;
        }
    }
}

// ---------------- K_post: 2 edges per block, 256 threads ----------------
__global__ void __launch_bounds__(256, 2)
k_post(const float* __restrict__ ec, const float* __restrict__ ef,
       const float* __restrict__ wo, const float* __restrict__ bo,
       const float* __restrict__ lg, const float* __restrict__ lb,
       float* __restrict__ out) {
    __shared__ float att[2][NHEAD][EN];    // 24.6 KB
    __shared__ float upd[2][HIDN];
    __shared__ float hsum[2][NHEAD][4];
    __shared__ float dacc[2][3];
    __shared__ float red[2][HIDN];

    int t = threadIdx.x;
    int lane = t & 31, w = t >> 5;
    int i0 = blockIdx.x * 2;

    // ---- phase 1: warp-local softmax; 16 tasks on 8 warps (2 each) ----
#pragma unroll
    for (int pass = 0; pass < 2; pass++) {
        int task = w + pass * 8;            // 0..15
        int e = task >> 3, h = task & 7;
        const float* srow = g_scores + ((long)h * EN + (i0 + e)) * EN;
        float s[12];
#pragma unroll
        for (int k = 0; k < 12; k++) s[k] = srow[lane + 32 * k];
        float m = s[0];
#pragma unroll
        for (int k = 1; k < 12; k++) m = fmaxf(m, s[k]);
#pragma unroll
        for (int off = 16; off > 0; off >>= 1)
            m = fmaxf(m, __shfl_xor_sync(0xffffffffu, m, off));
        float tot = 0.f;
#pragma unroll
        for (int k = 0; k < 12; k++) {
            s[k] = __expf(s[k] - m);
            tot += s[k];
        }
#pragma unroll
        for (int off = 16; off > 0; off >>= 1)
            tot += __shfl_xor_sync(0xffffffffu, tot, off);
        float inv = 1.0f / tot;
#pragma unroll
        for (int k = 0; k < 12; k++) att[e][h][lane + 32 * k] = s[k] * inv;
    }
    __syncthreads();

    // ---- phase 2: A@V (all 256 threads: e = t>>7, c = t&127) ----
    {
        int e = t >> 7, c = t & 127;
        int h = c >> 4;
        const float* ar = att[e][h];
        float acc = 0.f;
#pragma unroll 4
        for (int j = 0; j < EN; j++) acc = fmaf(ar[j], g_v[j * HIDN + c], acc);
        upd[e][c] = acc;
    }
    // ---- phase 2b: coord sums; 64 tasks x 4 sub-chunks ----
    {
        int task = t >> 2, sub = t & 3;     // 64 tasks
        int e = task >> 5, o = task & 31;
        int h = o >> 2, q = o & 3;
        const float* ar = att[e][h];
        float s2 = 0.f;
        if (q == 0) {
#pragma unroll 4
            for (int j = sub * 96; j < (sub + 1) * 96; j++) s2 += ar[j];
        } else {
            const float* cp = ec + (q - 1);
#pragma unroll 4
            for (int j = sub * 96; j < (sub + 1) * 96; j++)
                s2 = fmaf(ar[j], cp[j * 3], s2);
        }
        s2 += __shfl_xor_sync(0xffffffffu, s2, 1);
        s2 += __shfl_xor_sync(0xffffffffu, s2, 2);
        if (sub == 0) hsum[e][h][q] = s2;
    }
    __syncthreads();

    // ---- phase 3: coord delta ----
    if (t < 6) {
        int e = t / 3, ax = t % 3;
        int i = i0 + e;
        float d = 0.f;
#pragma unroll
        for (int h = 0; h < NHEAD; h++)
            d += g_gates[h * EN + i] * (hsum[e][h][0] * ec[i * 3 + ax] - hsum[e][h][1 + ax]);
        dacc[e][ax] = d;
    }
    __syncthreads();

    // ---- phase 4: output projection + layernorm (per-edge partitions) ----
    int e = t >> 7, c = t & 127;
    int i = i0 + e;
    float y = ef[i * HIDN + c] + bo[c];
#pragma unroll 8
    for (int cc = 0; cc < HIDN; cc++) y = fmaf(upd[e][cc], wo[cc * HIDN + c], y);
    red[e][c] = y;
    __syncthreads();
    for (int s2 = 64; s2 > 0; s2 >>= 1) {
        if (c < s2) red[e][c] += red[e][c + s2];
        __syncthreads();
    }
    float mean = red[e][0] * (1.0f / HIDN);
    __syncthreads();
    float dy = y - mean;
    red[e][c] = dy * dy;
    __syncthreads();
    for (int s2 = 64; s2 > 0; s2 >>= 1) {
        if (c < s2) red[e][c] += red[e][c + s2];
        __syncthreads();
    }
    float var = red[e][0] * (1.0f / HIDN);
    float rstd = rsqrtf(var + 1e-5f);
    out[i * HIDN + c] = dy * rstd * lg[c] + lb[c];
    if (t < 6) {
        int ee = t / 3, ax = t % 3;
        int ii = i0 + ee;
        out[EN * HIDN + ii * 3 + ax] = ec[ii * 3 + ax] + dacc[ee][ax] * 0.125f;
    }
}

// ---------------- launcher ----------------
extern "C" void kernel_launch(void* const* d_in, const int* in_sizes, int n_in,
                              void* d_out, int out_size) {
    const float* ef      = (const float*)d_in[0];
    const float* ec      = (const float*)d_in[1];
    const float* mask    = (const float*)d_in[2];
    const float* wq      = (const float*)d_in[3];
    const float* wk      = (const float*)d_in[4];
    const float* wv      = (const float*)d_in[5];
    const float* centers = (const float*)d_in[6];
    const float* widths  = (const float*)d_in[7];
    const float* a_w1    = (const float*)d_in[8];
    const float* a_b1    = (const float*)d_in[9];
    const float* a_w2    = (const float*)d_in[10];
    const float* a_b2    = (const float*)d_in[11];
    const float* a_w3    = (const float*)d_in[12];
    const float* a_b3    = (const float*)d_in[13];
    const float* g_w1    = (const float*)d_in[14];
    const float* g_b1    = (const float*)d_in[15];
    const float* g_w2    = (const float*)d_in[16];
    const float* g_b2    = (const float*)d_in[17];
    const float* wo      = (const float*)d_in[18];
    const float* bo      = (const float*)d_in[19];
    const float* ln_g    = (const float*)d_in[20];
    const float* ln_b    = (const float*)d_in[21];
    float* out = (float*)d_out;

    cudaFuncSetAttribute(k_scores, cudaFuncAttributeMaxDynamicSharedMemorySize,
                         SMEM_BYTES);

    k_pre<<<EN / 8 + 1, 1024>>>(ef, wq, wk, wv, a_w1, a_w2, g_w1, g_b1, g_w2, g_b2);
    k_scores<<<dim3(EN / 16, EN / 8), 1024, SMEM_BYTES>>>(
        ec, mask, centers, widths, a_w1, a_b1, a_b2, a_w3, a_b3);
    k_post<<<EN / 2, 256>>>(ec, ef, wo, bo, ln_g, ln_b, out);
}

// round 14
// speedup vs baseline: 1.0918x; 1.0918x over previous
#include <cuda_runtime.h>
#include <cuda_fp16.h>
#include <math.h>
#include <stdint.h>

#define EN 384
#define HIDN 128
#define NHEAD 8
#define DHEAD 16
#define NRBF 64

static constexpr int XROW = 272;  // fp16 tile row stride (bytes)
static constexpr int HROW = 320;  // fp16 HPRE row stride (bytes)

// ---- smem byte-offset map (dynamic smem, k_scores; 64-pair tile) ----
static constexpr int OFF_X1A  = 0;        // 64*272 = 17408
static constexpr int OFF_X1B  = 17408;    // 17408
static constexpr int OFF_W2H  = 34816;    // 128*272 = 34816
static constexpr int OFF_HPREH= 69632;    // 64*320 = 20480
static constexpr int OFF_SRED = 90112;    // 2*256*4 = 2048
static constexpr int OFF_B2S  = 92160;    // 512
static constexpr int OFF_W3S  = 92672;    // 4096
static constexpr int OFF_DISTS= 96768;    // 256
static constexpr int OFF_DOTS = 97024;    // 256
static constexpr int SMEM_BYTES = 97280;

// ---------------- device scratch ----------------
__device__ float g_v[EN * HIDN];
__device__ __half g_Aqh[NHEAD * EN * HIDN];
__device__ __half g_Akh[NHEAD * EN * HIDN];
__device__ __half g_W2h[HIDN * HIDN];
__device__ float g_gates[NHEAD * EN];
__device__ float g_scores[NHEAD * EN * EN];

__device__ __forceinline__ float siluf(float x) {
    return __fdividef(x, 1.0f + __expf(-x));
}
__device__ __forceinline__ uint32_t f16pair(float x0, float x1) {
    uint32_t u;
    asm("cvt.rn.f16x2.f32 %0, %1, %2;" : "=r"(u) : "f"(x1), "f"(x0));
    return u;
}
__device__ __forceinline__ uint32_t h2tanh(uint32_t y) {
    uint32_t r;
    asm("tanh.approx.f16x2 %0, %1;" : "=r"(r) : "r"(y));
    return r;
}
__device__ __forceinline__ uint32_t h2silu(uint32_t xb) {
    __half2 x = *(__half2*)&xb;
    __half2 y = __hmul2(x, __half2half2(__ushort_as_half(0x3800)));  // 0.5
    uint32_t yb = *(uint32_t*)&y;
    uint32_t tb = h2tanh(yb);
    __half2 t = *(__half2*)&tb;
    __half2 o = __hfma2(y, t, y);
    return *(uint32_t*)&o;
}
__device__ __forceinline__ uint32_t smem_u32(const void* p) {
    uint32_t a;
    asm("{ .reg .u64 t; cvta.to.shared.u64 t, %1; cvt.u32.u64 %0, t; }" : "=r"(a) : "l"(p));
    return a;
}

// ---- HMMA path ----
__device__ __forceinline__ void ldsm_x4(uint32_t* r, uint32_t addr) {
    asm volatile("ldmatrix.sync.aligned.m8n8.x4.shared.b16 {%0,%1,%2,%3}, [%4];"
                 : "=r"(r[0]), "=r"(r[1]), "=r"(r[2]), "=r"(r[3]) : "r"(addr));
}
__device__ __forceinline__ void ldsm_x4t(uint32_t* r, uint32_t addr) {
    asm volatile("ldmatrix.sync.aligned.m8n8.x4.trans.shared.b16 {%0,%1,%2,%3}, [%4];"
                 : "=r"(r[0]), "=r"(r[1]), "=r"(r[2]), "=r"(r[3]) : "r"(addr));
}
__device__ __forceinline__ void mma_f16(float* d, const uint32_t* a, uint32_t b0, uint32_t b1) {
    asm volatile(
        "mma.sync.aligned.m16n8k16.row.col.f32.f16.f16.f32 "
        "{%0,%1,%2,%3}, {%4,%5,%6,%7}, {%8,%9}, {%0,%1,%2,%3};"
        : "+f"(d[0]), "+f"(d[1]), "+f"(d[2]), "+f"(d[3])
        : "r"(a[0]), "r"(a[1]), "r"(a[2]), "r"(a[3]), "r"(b0), "r"(b1));
}

// ---------------- K_pre (R12 version): per-edge block, 256 threads, split halves ----------------
__global__ void __launch_bounds__(256, 4)
k_pre(const float* __restrict__ ef, const float* __restrict__ wq,
      const float* __restrict__ wk, const float* __restrict__ wv,
      const float* __restrict__ w1, const float* __restrict__ w2,
      const float* __restrict__ gw1, const float* __restrict__ gb1,
      const float* __restrict__ gw2, const float* __restrict__ gb2) {
    int i = blockIdx.x;
    if (i == EN) {   // W2 fp32 -> fp16 global, once
        for (int idx = threadIdx.x; idx < HIDN * HIDN; idx += 256)
            g_W2h[idx] = __float2half_rn(w2[idx]);
        return;
    }
    __shared__ float row[HIDN], qrow[HIDN], krow[HIDN], vrow[HIDN];
    __shared__ float wpart[4][NHEAD];
    int tid = threadIdx.x;
    int n = tid & 127, half = tid >> 7;
    int lane = tid & 31;
    if (tid < 128) row[tid] = ef[i * HIDN + tid];
    __syncthreads();

    if (half == 0) {
        float qa0 = 0.f, qa1 = 0.f, va0 = 0.f, va1 = 0.f;
#pragma unroll 4
        for (int c = 0; c < HIDN; c += 2) {
            float r0 = row[c], r1 = row[c + 1];
            qa0 = fmaf(r0, wq[c * HIDN + n], qa0);
            qa1 = fmaf(r1, wq[(c + 1) * HIDN + n], qa1);
            va0 = fmaf(r0, wv[c * HIDN + n], va0);
            va1 = fmaf(r1, wv[(c + 1) * HIDN + n], va1);
        }
        float qa = qa0 + qa1, va = va0 + va1;
        qrow[n] = qa; vrow[n] = va;
        g_v[i * HIDN + n] = va;
    } else {
        float ka0 = 0.f, ka1 = 0.f;
#pragma unroll 4
        for (int c = 0; c < HIDN; c += 2) {
            ka0 = fmaf(row[c], wk[c * HIDN + n], ka0);
            ka1 = fmaf(row[c + 1], wk[(c + 1) * HIDN + n], ka1);
        }
        krow[n] = ka0 + ka1;
    }
    __syncthreads();

    if (half == 0) {
#pragma unroll 1
        for (int h = 0; h < NHEAD; h++) {
            float aq = 0.f;
#pragma unroll
            for (int d = 0; d < DHEAD; d++)
                aq = fmaf(qrow[h * DHEAD + d], w1[d * HIDN + n], aq);
            g_Aqh[((long)h * EN + i) * HIDN + n] = __float2half_rn(aq);
        }
    } else {
#pragma unroll 1
        for (int h = 0; h < NHEAD; h++) {
            float ak = 0.f;
#pragma unroll
            for (int d = 0; d < DHEAD; d++)
                ak = fmaf(krow[h * DHEAD + d], w1[(DHEAD + d) * HIDN + n], ak);
            g_Akh[((long)h * EN + i) * HIDN + n] = __float2half_rn(ak);
        }
#pragma unroll 1
        for (int h = 0; h < NHEAD; h++) {
            float acc = gb1[n];
#pragma unroll
            for (int d = 0; d < DHEAD; d++)
                acc = fmaf(vrow[h * DHEAD + d], gw1[d * HIDN + n], acc);
            float val = siluf(acc) * gw2[n];
#pragma unroll
            for (int off = 16; off > 0; off >>= 1)
                val += __shfl_xor_sync(0xffffffffu, val, off);
            if (lane == 0) wpart[(tid >> 5) - 4][h] = val;
        }
    }
    __syncthreads();
    if (tid < NHEAD) {
        float s = wpart[0][tid] + wpart[1][tid] + wpart[2][tid] + wpart[3][tid];
        g_gates[tid * EN + i] = 1.0f / (1.0f + __expf(-(s + gb2[0])));
    }
}

// ---------------- K1: fused pair-MLP -> attention scores ----------------
// 64-pair tile (8i x 8j), 512 threads, 16 warps, 2 CTAs/SM.
// Warp tile 16x32: mb = w&3 (pair rows), nb = w>>2 (channel cols).
__global__ void __launch_bounds__(512, 2)
k_scores(const float* __restrict__ ec, const float* __restrict__ mask,
         const float* __restrict__ centers, const float* __restrict__ widths,
         const float* __restrict__ w1, const float* __restrict__ b1,
         const float* __restrict__ b2,
         const float* __restrict__ w3, const float* __restrict__ b3) {
    extern __shared__ float smem_f[];
    char* smem_c = (char*)smem_f;
    float* SRED  = (float*)(smem_c + OFF_SRED);
    float* B2S   = (float*)(smem_c + OFF_B2S);
    float* W3S   = (float*)(smem_c + OFF_W3S);
    float* dists = (float*)(smem_c + OFF_DISTS);
    float* dots  = (float*)(smem_c + OFF_DOTS);

    uint32_t sbase = smem_u32(smem_c);

    int tid = threadIdx.x;
    int w = tid >> 5, lane = tid & 31;
    int bi = blockIdx.x, bj = blockIdx.y;

    int p = tid >> 3;          // 0..63
    int lq = tid & 7;
    int ig_p = bi * 8 + (p >> 3);
    int jg_p = bj * 8 + (p & 7);

    // ---- pair geometry (64 pairs) ----
    if (tid < 64) {
        int pp = tid;
        int i = bi * 8 + (pp >> 3);
        int j = bj * 8 + (pp & 7);
        float ix = ec[i * 3], iy = ec[i * 3 + 1], iz = ec[i * 3 + 2];
        float jx = ec[j * 3], jy = ec[j * 3 + 1], jz = ec[j * 3 + 2];
        float dx = ix - jx, dy = iy - jy, dz = iz - jz;
        float d = sqrtf(dx * dx + dy * dy + dz * dz) + 1e-8f;
        d = fminf(fmaxf(d, 1e-8f), 1e8f);
        dists[pp] = d;
        float dt = ix * jx + iy * jy + iz * jz;
        dots[pp] = fminf(fmaxf(dt, -1e8f), 1e8f);
    }
    // ---- W2 fp16 from global ----
    for (int idx = tid; idx < HIDN * HIDN / 8; idx += 512) {
        int c = idx >> 4, col16 = idx & 15;
        *(uint4*)(smem_c + OFF_W2H + c * XROW + col16 * 16) =
            *(const uint4*)((const char*)g_W2h + idx * 16);
    }
    // ---- W1rbf -> fp16 [r][n] in X1B overlay ----
    for (int idx = tid; idx < NRBF * HIDN; idx += 512) {
        int r = idx >> 7, n = idx & 127;
        __half hv = __float2half_rn(w1[(2 * DHEAD + r) * HIDN + n]);
        *(unsigned short*)(smem_c + OFF_X1B + r * XROW + n * 2) = __half_as_ushort(hv);
    }
    if (tid < 128) B2S[tid] = b2[tid];
    for (int idx = tid; idx < HIDN * NHEAD; idx += 512) W3S[idx] = w3[idx];
    __syncthreads();

    // ---- rbf features fp16 [p][r] in X1A overlay (64 pairs) ----
    for (int idx = tid; idx < 64 * (NRBF / 2); idx += 512) {
        int pp = idx >> 5, rp = idx & 31;
        int r = 2 * rp;
        float d = dists[pp];
        float t0 = d - centers[r], t1 = d - centers[r + 1];
        float e0 = 0.f, e1 = 0.f;
        if (d <= 10.0f) {
            e0 = __expf(-widths[r] * t0 * t0);
            e1 = __expf(-widths[r + 1] * t1 * t1);
        }
        *(uint32_t*)(smem_c + OFF_X1A + pp * XROW + r * 2) = f16pair(e0, e1);
    }
    __syncthreads();

    // ---- HMMA tiling constants (16 warps: 16x32 tiles over 64x128) ----
    int mb = w & 3, nb = w >> 2;
    int r16 = lane & 15, rh = lane >> 4;
    uint32_t aTile = (uint32_t)(16 * mb + r16) * XROW + rh * 16;
    uint32_t bW1 = sbase + OFF_X1B + (uint32_t)r16 * XROW + 64 * nb + 16 * rh;
    uint32_t bHi = sbase + OFF_W2H + (uint32_t)r16 * XROW + 64 * nb + 16 * rh;

    // ---- rbf -> hpre via HMMA (K = 64) ----
    {
        uint32_t aRbf = sbase + OFF_X1A + aTile;
        float acc[4][4];
#pragma unroll
        for (int ni = 0; ni < 4; ni++)
#pragma unroll
            for (int e = 0; e < 4; e++) acc[ni][e] = 0.f;
#pragma unroll
        for (int kk = 0; kk < 4; kk++) {
            uint32_t ah[4], bh[2][4];
            ldsm_x4(ah, aRbf + kk * 32);
            ldsm_x4t(bh[0], bW1 + kk * 16 * XROW);
            ldsm_x4t(bh[1], bW1 + kk * 16 * XROW + 32);
#pragma unroll
            for (int bx = 0; bx < 2; bx++)
#pragma unroll
                for (int hf = 0; hf < 2; hf++) {
                    int ni = 2 * bx + hf;
                    mma_f16(acc[ni], ah, bh[bx][2 * hf], bh[bx][2 * hf + 1]);
                }
        }
        int r0 = 16 * mb + (lane >> 2);
        float dp0 = dots[r0], dp1 = dots[r0 + 8];
#pragma unroll
        for (int ni = 0; ni < 4; ni++) {
            int c0 = 32 * nb + 8 * ni + 2 * (lane & 3);
            float wd0 = __ldg(w1 + 96 * HIDN + c0), wd1 = __ldg(w1 + 96 * HIDN + c0 + 1);
            float b10 = __ldg(b1 + c0), b11 = __ldg(b1 + c0 + 1);
            float v00 = acc[ni][0] + dp0 * wd0 + b10;
            float v01 = acc[ni][1] + dp0 * wd1 + b11;
            float v10 = acc[ni][2] + dp1 * wd0 + b10;
            float v11 = acc[ni][3] + dp1 * wd1 + b11;
            *(uint32_t*)(smem_c + OFF_HPREH + r0 * HROW + c0 * 2) = f16pair(v00, v01);
            *(uint32_t*)(smem_c + OFF_HPREH + (r0 + 8) * HROW + c0 * 2) = f16pair(v10, v11);
        }
    }
    __syncthreads();   // HPREH done; overlays dead -> X1 buffers usable

    float mask_v = 0.f;
    int igw = 0, jgw = 0;
    if (tid < 64) {
        igw = bi * 8 + (tid >> 3);
        jgw = bj * 8 + (tid & 7);
        mask_v = __ldg(mask + (long)igw * EN + jgw);
    }

    const char* hpb = smem_c + OFF_HPREH + p * HROW;
    auto build_x1 = [&](int h, int sel) {
        char* dst = smem_c + (sel ? OFF_X1B : OFF_X1A) + p * XROW;
        const __half* aqp = g_Aqh + ((long)(h * EN + ig_p)) * HIDN;
        const __half* akp = g_Akh + ((long)(h * EN + jg_p)) * HIDN;
#pragma unroll
        for (int q = 0; q < 4; q++) {
            int c = lq * 4 + 32 * q;
            uint2 av = __ldg((const uint2*)(aqp + c));
            uint2 kv = __ldg((const uint2*)(akp + c));
            uint2 hv = *(const uint2*)(hpb + c * 2);
            __half2 x0 = __hadd2(__hadd2(*(__half2*)&hv.x, *(__half2*)&av.x),
                                 *(__half2*)&kv.x);
            __half2 x1 = __hadd2(__hadd2(*(__half2*)&hv.y, *(__half2*)&av.y),
                                 *(__half2*)&kv.y);
            uint32_t o0 = h2silu(*(uint32_t*)&x0);
            uint32_t o1 = h2silu(*(uint32_t*)&x1);
            *(uint2*)(dst + c * 2) = make_uint2(o0, o1);
        }
    };

    build_x1(0, 0);
    __syncthreads();

    for (int h = 0; h < NHEAD; h++) {
        int sel = h & 1;
        uint32_t aBuf = sbase + (sel ? OFF_X1B : OFF_X1A) + aTile;
        float acc[4][4];
#pragma unroll
        for (int ni = 0; ni < 4; ni++)
#pragma unroll
            for (int e = 0; e < 4; e++) acc[ni][e] = 0.f;

#pragma unroll
        for (int kk = 0; kk < 8; kk++) {
            uint32_t kab = (uint32_t)kk * 32;
            uint32_t kbb = (uint32_t)kk * 16 * XROW;
            uint32_t ah[4], bh[2][4];
            ldsm_x4(ah, aBuf + kab);
            ldsm_x4t(bh[0], bHi + kbb);
            ldsm_x4t(bh[1], bHi + kbb + 32);
#pragma unroll
            for (int bx = 0; bx < 2; bx++)
#pragma unroll
                for (int hf = 0; hf < 2; hf++) {
                    int ni = 2 * bx + hf;
                    mma_f16(acc[ni], ah, bh[bx][2 * hf], bh[bx][2 * hf + 1]);
                }
        }

        // ---- epilogue: packed fp16 silu + w3 reduce -> SRED[sel] ----
        {
            float* SR = SRED + sel * 256;
            int colq = 2 * (lane & 3);
            float s0 = 0.f, s1 = 0.f;
#pragma unroll
            for (int ni = 0; ni < 4; ni++) {
                int col = 32 * nb + 8 * ni + colq;
                float b2a = B2S[col], b2b = B2S[col + 1];
                float w3a = W3S[col * NHEAD + h], w3b = W3S[(col + 1) * NHEAD + h];
                uint32_t u0 = h2silu(f16pair(acc[ni][0] + b2a, acc[ni][1] + b2b));
                float2 f0 = __half22float2(*(__half2*)&u0);
                s0 += f0.x * w3a + f0.y * w3b;
                uint32_t u1 = h2silu(f16pair(acc[ni][2] + b2a, acc[ni][3] + b2b));
                float2 f1 = __half22float2(*(__half2*)&u1);
                s1 += f1.x * w3a + f1.y * w3b;
            }
#pragma unroll
            for (int off = 1; off < 4; off <<= 1) {
                s0 += __shfl_xor_sync(0xffffffffu, s0, off);
                s1 += __shfl_xor_sync(0xffffffffu, s1, off);
            }
            if ((lane & 3) == 0) {
                int r0 = 16 * mb + (lane >> 2);
                SR[nb * 64 + r0] = s0;
                SR[nb * 64 + r0 + 8] = s1;
            }
        }

        if (h < NHEAD - 1) build_x1(h + 1, sel ^ 1);

        __syncthreads();

        if (tid < 64) {
            float* SR = SRED + sel * 256;
            float tot = SR[tid] + SR[64 + tid] + SR[128 + tid] + SR[192 + tid];
            float sc = tot + b3[h] + mask_v;
            sc = fminf(fmaxf(sc, -1e9f), 1e9f);
            g_scores[((long)h * EN + igw) * EN + jgw] = sc;
        }
    }
}

// ---------------- K_post (R12 version): warp-local softmax + coalesced A@V ----------------
__global__ void __launch_bounds__(EN, 2)
k_post(const float* __restrict__ ec, const float* __restrict__ ef,
       const float* __restrict__ wo, const float* __restrict__ bo,
       const float* __restrict__ lg, const float* __restrict__ lb,
       float* __restrict__ out) {
    __shared__ float att[NHEAD][EN];
    __shared__ float upd[HIDN];
    __shared__ float hsum[NHEAD][4];
    __shared__ float dacc[3];
    __shared__ float red[128];

    int i = blockIdx.x, t = threadIdx.x;
    int lane = t & 31, w = t >> 5;

    if (w < NHEAD) {
        const float* srow = g_scores + ((long)w * EN + i) * EN;
        float s[12];
#pragma unroll
        for (int k = 0; k < 12; k++) s[k] = srow[lane + 32 * k];
        float m = s[0];
#pragma unroll
        for (int k = 1; k < 12; k++) m = fmaxf(m, s[k]);
#pragma unroll
        for (int off = 16; off > 0; off >>= 1)
            m = fmaxf(m, __shfl_xor_sync(0xffffffffu, m, off));
        float tot = 0.f;
#pragma unroll
        for (int k = 0; k < 12; k++) {
            s[k] = __expf(s[k] - m);
            tot += s[k];
        }
#pragma unroll
        for (int off = 16; off > 0; off >>= 1)
            tot += __shfl_xor_sync(0xffffffffu, tot, off);
        float inv = 1.0f / tot;
#pragma unroll
        for (int k = 0; k < 12; k++) att[w][lane + 32 * k] = s[k] * inv;
    }
    __syncthreads();

    if (t < 128) {
        int h = t >> 4;
        const float* ar = att[h];
        float acc = 0.f;
#pragma unroll 4
        for (int j = 0; j < EN; j++) acc = fmaf(ar[j], g_v[j * HIDN + t], acc);
        upd[t] = acc;
    } else if (t < 160) {
        int o = t - 128;
        int h = o >> 2, q = o & 3;
        const float* ar = att[h];
        float s2 = 0.f;
        if (q == 0) {
#pragma unroll 4
            for (int j = 0; j < EN; j++) s2 += ar[j];
        } else {
            const float* cp = ec + (q - 1);
#pragma unroll 4
            for (int j = 0; j < EN; j++) s2 = fmaf(ar[j], cp[j * 3], s2);
        }
        hsum[h][q] = s2;
    }
    __syncthreads();

    if (t < 3) {
        float d = 0.f;
#pragma unroll
        for (int h = 0; h < NHEAD; h++)
            d += g_gates[h * EN + i] * (hsum[h][0] * ec[i * 3 + t] - hsum[h][1 + t]);
        dacc[t] = d;
    }

    float y = 0.f;
    if (t < 128) {
        y = ef[i * HIDN + t] + bo[t];
#pragma unroll 8
        for (int c = 0; c < HIDN; c++) y = fmaf(upd[c], wo[c * HIDN + t], y);
        red[t] = y;
    }
    __syncthreads();
    for (int s2 = 64; s2 > 0; s2 >>= 1) {
        if (t < s2) red[t] += red[t + s2];
        __syncthreads();
    }
    float mean = red[0] * (1.0f / HIDN);
    __syncthreads();
    float dy = y - mean;
    if (t < 128) red[t] = dy * dy;
    __syncthreads();
    for (int s2 = 64; s2 > 0; s2 >>= 1) {
        if (t < s2) red[t] += red[t + s2];
        __syncthreads();
    }
    float var = red[0] * (1.0f / HIDN);
    float rstd = rsqrtf(var + 1e-5f);
    if (t < 128) out[i * HIDN + t] = dy * rstd * lg[t] + lb[t];
    if (t < 3) out[EN * HIDN + i * 3 + t] = ec[i * 3 + t] + dacc[t] * 0.125f;
}

// ---------------- launcher ----------------
extern "C" void kernel_launch(void* const* d_in, const int* in_sizes, int n_in,
                              void* d_out, int out_size) {
    const float* ef      = (const float*)d_in[0];
    const float* ec      = (const float*)d_in[1];
    const float* mask    = (const float*)d_in[2];
    const float* wq      = (const float*)d_in[3];
    const float* wk      = (const float*)d_in[4];
    const float* wv      = (const float*)d_in[5];
    const float* centers = (const float*)d_in[6];
    const float* widths  = (const float*)d_in[7];
    const float* a_w1    = (const float*)d_in[8];
    const float* a_b1    = (const float*)d_in[9];
    const float* a_w2    = (const float*)d_in[10];
    const float* a_b2    = (const float*)d_in[11];
    const float* a_w3    = (const float*)d_in[12];
    const float* a_b3    = (const float*)d_in[13];
    const float* g_w1    = (const float*)d_in[14];
    const float* g_b1    = (const float*)d_in[15];
    const float* g_w2    = (const float*)d_in[16];
    const float* g_b2    = (const float*)d_in[17];
    const float* wo      = (const float*)d_in[18];
    const float* bo      = (const float*)d_in[19];
    const float* ln_g    = (const float*)d_in[20];
    const float* ln_b    = (const float*)d_in[21];
    float* out = (float*)d_out;

    cudaFuncSetAttribute(k_scores, cudaFuncAttributeMaxDynamicSharedMemorySize,
                         SMEM_BYTES);

    k_pre<<<EN + 1, 256>>>(ef, wq, wk, wv, a_w1, a_w2, g_w1, g_b1, g_w2, g_b2);
    k_scores<<<dim3(EN / 8, EN / 8), 512, SMEM_BYTES>>>(
        ec, mask, centers, widths, a_w1, a_b1, a_b2, a_w3, a_b3);
    k_post<<<EN, EN>>>(ec, ef, wo, bo, ln_g, ln_b, out);
}

// round 15
// speedup vs baseline: 1.1690x; 1.0707x over previous
#include <cuda_runtime.h>
#include <cuda_fp16.h>
#include <math.h>
#include <stdint.h>

#define EN 384
#define HIDN 128
#define NHEAD 8
#define DHEAD 16
#define NRBF 64

static constexpr int XROW = 272;  // fp16 tile row stride (bytes)
static constexpr int HROW = 320;  // fp16 HPRE row stride (bytes)
static constexpr int NTILE_I = EN / 8;        // 48
static constexpr int NTILES = NTILE_I * NTILE_I;   // 2304
static constexpr int PGRID = 296;             // persistent CTAs (2 per SM)

// ---- smem byte-offset map (dynamic smem, k_scores persistent) ----
static constexpr int OFF_X1A  = 0;        // 64*272 = 17408
static constexpr int OFF_X1B  = 17408;    // 17408
static constexpr int OFF_W2H  = 34816;    // 128*272 = 34816
static constexpr int OFF_W1R  = 69632;    // 64*272 = 17408 (persists across tiles)
static constexpr int OFF_HPREH= 87040;    // 64*320 = 20480
static constexpr int OFF_SRED = 107520;   // 2*256*4 = 2048
static constexpr int OFF_B2S  = 109568;   // 512
static constexpr int OFF_W3S  = 110080;   // 4096
static constexpr int OFF_DISTS= 114176;   // 256
static constexpr int OFF_DOTS = 114432;   // 256
static constexpr int SMEM_BYTES = 114688;

// ---------------- device scratch ----------------
__device__ float g_v[EN * HIDN];
__device__ __half g_Aqh[NHEAD * EN * HIDN];
__device__ __half g_Akh[NHEAD * EN * HIDN];
__device__ __half g_W2h[HIDN * HIDN];
__device__ float g_gates[NHEAD * EN];
__device__ float g_scores[NHEAD * EN * EN];

__device__ __forceinline__ float siluf(float x) {
    return __fdividef(x, 1.0f + __expf(-x));
}
__device__ __forceinline__ uint32_t f16pair(float x0, float x1) {
    uint32_t u;
    asm("cvt.rn.f16x2.f32 %0, %1, %2;" : "=r"(u) : "f"(x1), "f"(x0));
    return u;
}
__device__ __forceinline__ uint32_t h2tanh(uint32_t y) {
    uint32_t r;
    asm("tanh.approx.f16x2 %0, %1;" : "=r"(r) : "r"(y));
    return r;
}
__device__ __forceinline__ uint32_t h2silu(uint32_t xb) {
    __half2 x = *(__half2*)&xb;
    __half2 y = __hmul2(x, __half2half2(__ushort_as_half(0x3800)));  // 0.5
    uint32_t yb = *(uint32_t*)&y;
    uint32_t tb = h2tanh(yb);
    __half2 t = *(__half2*)&tb;
    __half2 o = __hfma2(y, t, y);
    return *(uint32_t*)&o;
}
__device__ __forceinline__ uint32_t smem_u32(const void* p) {
    uint32_t a;
    asm("{ .reg .u64 t; cvta.to.shared.u64 t, %1; cvt.u32.u64 %0, t; }" : "=r"(a) : "l"(p));
    return a;
}

// ---- HMMA path ----
__device__ __forceinline__ void ldsm_x4(uint32_t* r, uint32_t addr) {
    asm volatile("ldmatrix.sync.aligned.m8n8.x4.shared.b16 {%0,%1,%2,%3}, [%4];"
                 : "=r"(r[0]), "=r"(r[1]), "=r"(r[2]), "=r"(r[3]) : "r"(addr));
}
__device__ __forceinline__ void ldsm_x4t(uint32_t* r, uint32_t addr) {
    asm volatile("ldmatrix.sync.aligned.m8n8.x4.trans.shared.b16 {%0,%1,%2,%3}, [%4];"
                 : "=r"(r[0]), "=r"(r[1]), "=r"(r[2]), "=r"(r[3]) : "r"(addr));
}
__device__ __forceinline__ void mma_f16(float* d, const uint32_t* a, uint32_t b0, uint32_t b1) {
    asm volatile(
        "mma.sync.aligned.m16n8k16.row.col.f32.f16.f16.f32 "
        "{%0,%1,%2,%3}, {%4,%5,%6,%7}, {%8,%9}, {%0,%1,%2,%3};"
        : "+f"(d[0]), "+f"(d[1]), "+f"(d[2]), "+f"(d[3])
        : "r"(a[0]), "r"(a[1]), "r"(a[2]), "r"(a[3]), "r"(b0), "r"(b1));
}

// ---------------- K_pre (unchanged, proven): per-edge block, 256 threads ----------------
__global__ void __launch_bounds__(256, 4)
k_pre(const float* __restrict__ ef, const float* __restrict__ wq,
      const float* __restrict__ wk, const float* __restrict__ wv,
      const float* __restrict__ w1, const float* __restrict__ w2,
      const float* __restrict__ gw1, const float* __restrict__ gb1,
      const float* __restrict__ gw2, const float* __restrict__ gb2) {
    int i = blockIdx.x;
    if (i == EN) {
        for (int idx = threadIdx.x; idx < HIDN * HIDN; idx += 256)
            g_W2h[idx] = __float2half_rn(w2[idx]);
        return;
    }
    __shared__ float row[HIDN], qrow[HIDN], krow[HIDN], vrow[HIDN];
    __shared__ float wpart[4][NHEAD];
    int tid = threadIdx.x;
    int n = tid & 127, half = tid >> 7;
    int lane = tid & 31;
    if (tid < 128) row[tid] = ef[i * HIDN + tid];
    __syncthreads();

    if (half == 0) {
        float qa0 = 0.f, qa1 = 0.f, va0 = 0.f, va1 = 0.f;
#pragma unroll 4
        for (int c = 0; c < HIDN; c += 2) {
            float r0 = row[c], r1 = row[c + 1];
            qa0 = fmaf(r0, wq[c * HIDN + n], qa0);
            qa1 = fmaf(r1, wq[(c + 1) * HIDN + n], qa1);
            va0 = fmaf(r0, wv[c * HIDN + n], va0);
            va1 = fmaf(r1, wv[(c + 1) * HIDN + n], va1);
        }
        float qa = qa0 + qa1, va = va0 + va1;
        qrow[n] = qa; vrow[n] = va;
        g_v[i * HIDN + n] = va;
    } else {
        float ka0 = 0.f, ka1 = 0.f;
#pragma unroll 4
        for (int c = 0; c < HIDN; c += 2) {
            ka0 = fmaf(row[c], wk[c * HIDN + n], ka0);
            ka1 = fmaf(row[c + 1], wk[(c + 1) * HIDN + n], ka1);
        }
        krow[n] = ka0 + ka1;
    }
    __syncthreads();

    if (half == 0) {
#pragma unroll 1
        for (int h = 0; h < NHEAD; h++) {
            float aq = 0.f;
#pragma unroll
            for (int d = 0; d < DHEAD; d++)
                aq = fmaf(qrow[h * DHEAD + d], w1[d * HIDN + n], aq);
            g_Aqh[((long)h * EN + i) * HIDN + n] = __float2half_rn(aq);
        }
    } else {
#pragma unroll 1
        for (int h = 0; h < NHEAD; h++) {
            float ak = 0.f;
#pragma unroll
            for (int d = 0; d < DHEAD; d++)
                ak = fmaf(krow[h * DHEAD + d], w1[(DHEAD + d) * HIDN + n], ak);
            g_Akh[((long)h * EN + i) * HIDN + n] = __float2half_rn(ak);
        }
#pragma unroll 1
        for (int h = 0; h < NHEAD; h++) {
            float acc = gb1[n];
#pragma unroll
            for (int d = 0; d < DHEAD; d++)
                acc = fmaf(vrow[h * DHEAD + d], gw1[d * HIDN + n], acc);
            float val = siluf(acc) * gw2[n];
#pragma unroll
            for (int off = 16; off > 0; off >>= 1)
                val += __shfl_xor_sync(0xffffffffu, val, off);
            if (lane == 0) wpart[(tid >> 5) - 4][h] = val;
        }
    }
    __syncthreads();
    if (tid < NHEAD) {
        float s = wpart[0][tid] + wpart[1][tid] + wpart[2][tid] + wpart[3][tid];
        g_gates[tid * EN + i] = 1.0f / (1.0f + __expf(-(s + gb2[0])));
    }
}

// ---------------- K1: persistent fused pair-MLP -> scores ----------------
// 296 CTAs x 512 threads, 2 CTAs/SM; each CTA loops over tiles (8i x 8j pairs).
__global__ void __launch_bounds__(512, 2)
k_scores(const float* __restrict__ ec, const float* __restrict__ mask,
         const float* __restrict__ centers, const float* __restrict__ widths,
         const float* __restrict__ w1, const float* __restrict__ b1,
         const float* __restrict__ b2,
         const float* __restrict__ w3, const float* __restrict__ b3) {
    extern __shared__ float smem_f[];
    char* smem_c = (char*)smem_f;
    float* SRED  = (float*)(smem_c + OFF_SRED);
    float* B2S   = (float*)(smem_c + OFF_B2S);
    float* W3S   = (float*)(smem_c + OFF_W3S);
    float* dists = (float*)(smem_c + OFF_DISTS);
    float* dots  = (float*)(smem_c + OFF_DOTS);

    uint32_t sbase = smem_u32(smem_c);

    int tid = threadIdx.x;
    int w = tid >> 5, lane = tid & 31;
    int p = tid >> 3;          // 0..63
    int lq = tid & 7;

    // ---- once-per-CTA setup ----
    for (int idx = tid; idx < HIDN * HIDN / 8; idx += 512) {
        int c = idx >> 4, col16 = idx & 15;
        *(uint4*)(smem_c + OFF_W2H + c * XROW + col16 * 16) =
            *(const uint4*)((const char*)g_W2h + idx * 16);
    }
    for (int idx = tid; idx < NRBF * HIDN; idx += 512) {
        int r = idx >> 7, n = idx & 127;
        __half hv = __float2half_rn(w1[(2 * DHEAD + r) * HIDN + n]);
        *(unsigned short*)(smem_c + OFF_W1R + r * XROW + n * 2) = __half_as_ushort(hv);
    }
    if (tid < 128) B2S[tid] = b2[tid];
    for (int idx = tid; idx < HIDN * NHEAD; idx += 512) W3S[idx] = w3[idx];

    // HMMA tiling constants (16 warps: 16x32 tiles over 64x128)
    int mb = w & 3, nb = w >> 2;
    int r16 = lane & 15, rh = lane >> 4;
    uint32_t aTile = (uint32_t)(16 * mb + r16) * XROW + rh * 16;
    uint32_t bW1 = sbase + OFF_W1R + (uint32_t)r16 * XROW + 64 * nb + 16 * rh;
    uint32_t bHi = sbase + OFF_W2H + (uint32_t)r16 * XROW + 64 * nb + 16 * rh;
    const char* hpb = smem_c + OFF_HPREH + p * HROW;

    for (int tile = blockIdx.x; tile < NTILES; tile += PGRID) {
        int bi = tile / NTILE_I, bj = tile % NTILE_I;
        int ig_p = bi * 8 + (p >> 3);
        int jg_p = bj * 8 + (p & 7);

        __syncthreads();   // previous tile fully done (X1A reads, SRED reads)

        // ---- pair geometry ----
        if (tid < 64) {
            int pp = tid;
            int i = bi * 8 + (pp >> 3);
            int j = bj * 8 + (pp & 7);
            float ix = ec[i * 3], iy = ec[i * 3 + 1], iz = ec[i * 3 + 2];
            float jx = ec[j * 3], jy = ec[j * 3 + 1], jz = ec[j * 3 + 2];
            float dx = ix - jx, dy = iy - jy, dz = iz - jz;
            float d = sqrtf(dx * dx + dy * dy + dz * dz) + 1e-8f;
            d = fminf(fmaxf(d, 1e-8f), 1e8f);
            dists[pp] = d;
            float dt = ix * jx + iy * jy + iz * jz;
            dots[pp] = fminf(fmaxf(dt, -1e8f), 1e8f);
        }
        __syncthreads();   // dists visible (also covers once-per-CTA setup on iter 0)

        // ---- rbf features fp16 [p][r] -> X1A overlay ----
        for (int idx = tid; idx < 64 * (NRBF / 2); idx += 512) {
            int pp = idx >> 5, rp = idx & 31;
            int r = 2 * rp;
            float d = dists[pp];
            float t0 = d - centers[r], t1 = d - centers[r + 1];
            float e0 = 0.f, e1 = 0.f;
            if (d <= 10.0f) {
                e0 = __expf(-widths[r] * t0 * t0);
                e1 = __expf(-widths[r + 1] * t1 * t1);
            }
            *(uint32_t*)(smem_c + OFF_X1A + pp * XROW + r * 2) = f16pair(e0, e1);
        }
        __syncthreads();

        // ---- rbf -> hpre via HMMA (K = 64) ----
        {
            uint32_t aRbf = sbase + OFF_X1A + aTile;
            float acc[4][4];
#pragma unroll
            for (int ni = 0; ni < 4; ni++)
#pragma unroll
                for (int e = 0; e < 4; e++) acc[ni][e] = 0.f;
#pragma unroll
            for (int kk = 0; kk < 4; kk++) {
                uint32_t ah[4], bh[2][4];
                ldsm_x4(ah, aRbf + kk * 32);
                ldsm_x4t(bh[0], bW1 + kk * 16 * XROW);
                ldsm_x4t(bh[1], bW1 + kk * 16 * XROW + 32);
#pragma unroll
                for (int bx = 0; bx < 2; bx++)
#pragma unroll
                    for (int hf = 0; hf < 2; hf++) {
                        int ni = 2 * bx + hf;
                        mma_f16(acc[ni], ah, bh[bx][2 * hf], bh[bx][2 * hf + 1]);
                    }
            }
            int r0 = 16 * mb + (lane >> 2);
            float dp0 = dots[r0], dp1 = dots[r0 + 8];
#pragma unroll
            for (int ni = 0; ni < 4; ni++) {
                int c0 = 32 * nb + 8 * ni + 2 * (lane & 3);
                float wd0 = __ldg(w1 + 96 * HIDN + c0), wd1 = __ldg(w1 + 96 * HIDN + c0 + 1);
                float b10 = __ldg(b1 + c0), b11 = __ldg(b1 + c0 + 1);
                float v00 = acc[ni][0] + dp0 * wd0 + b10;
                float v01 = acc[ni][1] + dp0 * wd1 + b11;
                float v10 = acc[ni][2] + dp1 * wd0 + b10;
                float v11 = acc[ni][3] + dp1 * wd1 + b11;
                *(uint32_t*)(smem_c + OFF_HPREH + r0 * HROW + c0 * 2) = f16pair(v00, v01);
                *(uint32_t*)(smem_c + OFF_HPREH + (r0 + 8) * HROW + c0 * 2) = f16pair(v10, v11);
            }
        }
        __syncthreads();   // HPREH done; X1A free

        float mask_v = 0.f;
        int igw = 0, jgw = 0;
        if (tid < 64) {
            igw = bi * 8 + (tid >> 3);
            jgw = bj * 8 + (tid & 7);
            mask_v = __ldg(mask + (long)igw * EN + jgw);
        }

        auto build_x1 = [&](int h, int sel) {
            char* dst = smem_c + (sel ? OFF_X1B : OFF_X1A) + p * XROW;
            const __half* aqp = g_Aqh + ((long)(h * EN + ig_p)) * HIDN;
            const __half* akp = g_Akh + ((long)(h * EN + jg_p)) * HIDN;
#pragma unroll
            for (int q = 0; q < 4; q++) {
                int c = lq * 4 + 32 * q;
                uint2 av = __ldg((const uint2*)(aqp + c));
                uint2 kv = __ldg((const uint2*)(akp + c));
                uint2 hv = *(const uint2*)(hpb + c * 2);
                __half2 x0 = __hadd2(__hadd2(*(__half2*)&hv.x, *(__half2*)&av.x),
                                     *(__half2*)&kv.x);
                __half2 x1 = __hadd2(__hadd2(*(__half2*)&hv.y, *(__half2*)&av.y),
                                     *(__half2*)&kv.y);
                uint32_t o0 = h2silu(*(uint32_t*)&x0);
                uint32_t o1 = h2silu(*(uint32_t*)&x1);
                *(uint2*)(dst + c * 2) = make_uint2(o0, o1);
            }
        };

        build_x1(0, 0);
        __syncthreads();

        for (int h = 0; h < NHEAD; h++) {
            int sel = h & 1;
            uint32_t aBuf = sbase + (sel ? OFF_X1B : OFF_X1A) + aTile;
            float acc[4][4];
#pragma unroll
            for (int ni = 0; ni < 4; ni++)
#pragma unroll
                for (int e = 0; e < 4; e++) acc[ni][e] = 0.f;

#pragma unroll
            for (int kk = 0; kk < 8; kk++) {
                uint32_t kab = (uint32_t)kk * 32;
                uint32_t kbb = (uint32_t)kk * 16 * XROW;
                uint32_t ah[4], bh[2][4];
                ldsm_x4(ah, aBuf + kab);
                ldsm_x4t(bh[0], bHi + kbb);
                ldsm_x4t(bh[1], bHi + kbb + 32);
#pragma unroll
                for (int bx = 0; bx < 2; bx++)
#pragma unroll
                    for (int hf = 0; hf < 2; hf++) {
                        int ni = 2 * bx + hf;
                        mma_f16(acc[ni], ah, bh[bx][2 * hf], bh[bx][2 * hf + 1]);
                    }
            }

            // epilogue: packed fp16 silu + w3 reduce -> SRED[sel]
            {
                float* SR = SRED + sel * 256;
                int colq = 2 * (lane & 3);
                float s0 = 0.f, s1 = 0.f;
#pragma unroll
                for (int ni = 0; ni < 4; ni++) {
                    int col = 32 * nb + 8 * ni + colq;
                    float b2a = B2S[col], b2b = B2S[col + 1];
                    float w3a = W3S[col * NHEAD + h], w3b = W3S[(col + 1) * NHEAD + h];
                    uint32_t u0 = h2silu(f16pair(acc[ni][0] + b2a, acc[ni][1] + b2b));
                    float2 f0 = __half22float2(*(__half2*)&u0);
                    s0 += f0.x * w3a + f0.y * w3b;
                    uint32_t u1 = h2silu(f16pair(acc[ni][2] + b2a, acc[ni][3] + b2b));
                    float2 f1 = __half22float2(*(__half2*)&u1);
                    s1 += f1.x * w3a + f1.y * w3b;
                }
#pragma unroll
                for (int off = 1; off < 4; off <<= 1) {
                    s0 += __shfl_xor_sync(0xffffffffu, s0, off);
                    s1 += __shfl_xor_sync(0xffffffffu, s1, off);
                }
                if ((lane & 3) == 0) {
                    int r0 = 16 * mb + (lane >> 2);
                    SR[nb * 64 + r0] = s0;
                    SR[nb * 64 + r0 + 8] = s1;
                }
            }

            if (h < NHEAD - 1) build_x1(h + 1, sel ^ 1);

            __syncthreads();

            if (tid < 64) {
                float* SR = SRED + sel * 256;
                float tot = SR[tid] + SR[64 + tid] + SR[128 + tid] + SR[192 + tid];
                float sc = tot + b3[h] + mask_v;
                sc = fminf(fmaxf(sc, -1e9f), 1e9f);
                g_scores[((long)h * EN + igw) * EN + jgw] = sc;
            }
        }
    }
}

// ---------------- K_post (unchanged, proven) ----------------
__global__ void __launch_bounds__(EN, 2)
k_post(const float* __restrict__ ec, const float* __restrict__ ef,
       const float* __restrict__ wo, const float* __restrict__ bo,
       const float* __restrict__ lg, const float* __restrict__ lb,
       float* __restrict__ out) {
    __shared__ float att[NHEAD][EN];
    __shared__ float upd[HIDN];
    __shared__ float hsum[NHEAD][4];
    __shared__ float dacc[3];
    __shared__ float red[128];

    int i = blockIdx.x, t = threadIdx.x;
    int lane = t & 31, w = t >> 5;

    if (w < NHEAD) {
        const float* srow = g_scores + ((long)w * EN + i) * EN;
        float s[12];
#pragma unroll
        for (int k = 0; k < 12; k++) s[k] = srow[lane + 32 * k];
        float m = s[0];
#pragma unroll
        for (int k = 1; k < 12; k++) m = fmaxf(m, s[k]);
#pragma unroll
        for (int off = 16; off > 0; off >>= 1)
            m = fmaxf(m, __shfl_xor_sync(0xffffffffu, m, off));
        float tot = 0.f;
#pragma unroll
        for (int k = 0; k < 12; k++) {
            s[k] = __expf(s[k] - m);
            tot += s[k];
        }
#pragma unroll
        for (int off = 16; off > 0; off >>= 1)
            tot += __shfl_xor_sync(0xffffffffu, tot, off);
        float inv = 1.0f / tot;
#pragma unroll
        for (int k = 0; k < 12; k++) att[w][lane + 32 * k] = s[k] * inv;
    }
    __syncthreads();

    if (t < 128) {
        int h = t >> 4;
        const float* ar = att[h];
        float acc = 0.f;
#pragma unroll 4
        for (int j = 0; j < EN; j++) acc = fmaf(ar[j], g_v[j * HIDN + t], acc);
        upd[t] = acc;
    } else if (t < 160) {
        int o = t - 128;
        int h = o >> 2, q = o & 3;
        const float* ar = att[h];
        float s2 = 0.f;
        if (q == 0) {
#pragma unroll 4
            for (int j = 0; j < EN; j++) s2 += ar[j];
        } else {
            const float* cp = ec + (q - 1);
#pragma unroll 4
            for (int j = 0; j < EN; j++) s2 = fmaf(ar[j], cp[j * 3], s2);
        }
        hsum[h][q] = s2;
    }
    __syncthreads();

    if (t < 3) {
        float d = 0.f;
#pragma unroll
        for (int h = 0; h < NHEAD; h++)
            d += g_gates[h * EN + i] * (hsum[h][0] * ec[i * 3 + t] - hsum[h][1 + t]);
        dacc[t] = d;
    }

    float y = 0.f;
    if (t < 128) {
        y = ef[i * HIDN + t] + bo[t];
#pragma unroll 8
        for (int c = 0; c < HIDN; c++) y = fmaf(upd[c], wo[c * HIDN + t], y);
        red[t] = y;
    }
    __syncthreads();
    for (int s2 = 64; s2 > 0; s2 >>= 1) {
        if (t < s2) red[t] += red[t + s2];
        __syncthreads();
    }
    float mean = red[0] * (1.0f / HIDN);
    __syncthreads();
    float dy = y - mean;
    if (t < 128) red[t] = dy * dy;
    __syncthreads();
    for (int s2 = 64; s2 > 0; s2 >>= 1) {
        if (t < s2) red[t] += red[t + s2];
        __syncthreads();
    }
    float var = red[0] * (1.0f / HIDN);
    float rstd = rsqrtf(var + 1e-5f);
    if (t < 128) out[i * HIDN + t] = dy * rstd * lg[t] + lb[t];
    if (t < 3) out[EN * HIDN + i * 3 + t] = ec[i * 3 + t] + dacc[t] * 0.125f;
}

// ---------------- launcher ----------------
extern "C" void kernel_launch(void* const* d_in, const int* in_sizes, int n_in,
                              void* d_out, int out_size) {
    const float* ef      = (const float*)d_in[0];
    const float* ec      = (const float*)d_in[1];
    const float* mask    = (const float*)d_in[2];
    const float* wq      = (const float*)d_in[3];
    const float* wk      = (const float*)d_in[4];
    const float* wv      = (const float*)d_in[5];
    const float* centers = (const float*)d_in[6];
    const float* widths  = (const float*)d_in[7];
    const float* a_w1    = (const float*)d_in[8];
    const float* a_b1    = (const float*)d_in[9];
    const float* a_w2    = (const float*)d_in[10];
    const float* a_b2    = (const float*)d_in[11];
    const float* a_w3    = (const float*)d_in[12];
    const float* a_b3    = (const float*)d_in[13];
    const float* g_w1    = (const float*)d_in[14];
    const float* g_b1    = (const float*)d_in[15];
    const float* g_w2    = (const float*)d_in[16];
    const float* g_b2    = (const float*)d_in[17];
    const float* wo      = (const float*)d_in[18];
    const float* bo      = (const float*)d_in[19];
    const float* ln_g    = (const float*)d_in[20];
    const float* ln_b    = (const float*)d_in[21];
    float* out = (float*)d_out;

    cudaFuncSetAttribute(k_scores, cudaFuncAttributeMaxDynamicSharedMemorySize,
                         SMEM_BYTES);

    k_pre<<<EN + 1, 256>>>(ef, wq, wk, wv, a_w1, a_w2, g_w1, g_b1, g_w2, g_b2);
    k_scores<<<PGRID, 512, SMEM_BYTES>>>(
        ec, mask, centers, widths, a_w1, a_b1, a_b2, a_w3, a_b3);
    k_post<<<EN, EN>>>(ec, ef, wo, bo, ln_g, ln_b, out);
}